// round 1
// baseline (speedup 1.0000x reference)
#include <cuda_runtime.h>

// RamanAmplifier: 4096 independent RK4 integrations of dP/dt = (G P - loss) .* P
// G is 104x104 per batch element (4 pump rows/cols batch-dependent, rest fixed),
// computed once into registers; P lives in shared memory, double-buffered per stage.

#define NP 4
#define NC 100
#define NT 104          // pumps + channels
#define NPAD 112        // padded row length (28*4)
#define SLICE 28        // j-columns per lane
#define THREADS 416     // 104 rows x 4 lanes = 13 warps
#define NSTEPS 499      // STEPS-1
#define RESP_LEN 801

__global__ __launch_bounds__(THREADS, 2)
void raman_kernel(const float* __restrict__ x,
                  const float* __restrict__ rr,
                  const float* __restrict__ swl,
                  float* __restrict__ out)
{
    __shared__ float sF[NPAD];          // frequencies
    __shared__ float sP[NPAD];          // current power
    __shared__ float sA[NPAD];          // stage arg buffer A
    __shared__ float sB[NPAD];          // stage arg buffer B
    __shared__ float sRR[RESP_LEN];     // raman response copy

    const int b    = blockIdx.x;
    const int tid  = threadIdx.x;
    const int r    = tid >> 2;          // row 0..103
    const int lane = tid & 3;           // j-lane 0..3
    const int j0   = lane * SLICE;

    const float* xb = x + b * (2 * NP);

    // ---- init: raman response into shared ----
    for (int i = tid; i < RESP_LEN; i += THREADS) sRR[i] = rr[i];

    // ---- init: frequencies, initial power, buffer pads ----
    if (tid < NPAD) {
        float f = 0.f, p0 = 0.f;
        if (tid < NT) {
            float lam = (tid < NP) ? xb[tid] : swl[tid - NP];
            f  = __fdiv_rn(299792458.0f, lam);
            p0 = (tid < NP) ? fabsf(xb[NP + tid]) : 0.001f;
        }
        sF[tid] = f;
        sP[tid] = p0;
        sA[tid] = p0;
        sB[tid] = 0.f;
    }
    __syncthreads();

    // ---- loss for this row: (c2 + c1*lam + c0*lam^2) * ln(10)/10, c0=c1=0 ----
    const float loss = 0.0002f * 0.23025851f;   // 4.60517e-5

    // ---- compute G row slice into registers ----
    float G[SLICE];
    const float fr = sF[r];
    #pragma unroll
    for (int u = 0; u < SLICE; u++) {
        int j = j0 + u;
        float gv = 0.f;
        if (j < NT) {
            float fj   = sF[j];
            float D    = fj - fr;                                    // freqs[j]-freqs[i]
            float fidx = __fdiv_rn(fabsf(D), 50000000000.0f);        // |D| / DF
            float fi0  = floorf(fidx);
            if (fi0 > 799.f) fi0 = 799.f;
            int   i0   = (int)fi0;
            float w    = fidx - fi0;
            float g    = sRR[i0] * (1.f - w) + sRR[i0 + 1] * w;
            if (D < 0.f) g = -g;
            float ratio = __fdiv_rn(fr, fj);                         // freqs[i]/freqs[j]
            gv = __fdiv_rn(g * fmaxf(1.f, ratio), 8e-11f);           // / EFFECTIVE_AREA
        }
        G[u] = gv;
    }
    __syncthreads();

    // ---- RK4 constants (mirror JAX: python-double scalars rounded to f32) ----
    const double dzd = 50000.0 / 499.0;
    const float  dz       = (float)dzd;
    const float  half_dz  = (float)(0.5 * dzd);
    const float  sixth_dz = (float)(dzd / 6.0);

    // deriv for this row given stage-arg buffer: (G[r,:].arg - loss) * arg[r]
    auto deriv = [&](const float* buf) -> float {
        float a0 = 0.f, a1 = 0.f, a2 = 0.f, a3 = 0.f;
        const float4* v = reinterpret_cast<const float4*>(buf + j0);
        #pragma unroll
        for (int u = 0; u < SLICE / 4; u++) {
            float4 p = v[u];
            a0 = fmaf(G[4*u + 0], p.x, a0);
            a1 = fmaf(G[4*u + 1], p.y, a1);
            a2 = fmaf(G[4*u + 2], p.z, a2);
            a3 = fmaf(G[4*u + 3], p.w, a3);
        }
        float dot = (a0 + a1) + (a2 + a3);
        dot += __shfl_xor_sync(0xffffffffu, dot, 1);
        dot += __shfl_xor_sync(0xffffffffu, dot, 2);
        return (dot - loss) * buf[r];
    };

    // ---- main RK4 loop ----
    for (int step = 0; step < NSTEPS; step++) {
        float d1 = deriv(sA);
        if (lane == 0) sB[r] = fmaf(half_dz, d1, sP[r]);
        __syncthreads();

        float d2 = deriv(sB);
        if (lane == 0) sA[r] = fmaf(half_dz, d2, sP[r]);
        __syncthreads();

        float d3 = deriv(sA);
        if (lane == 0) sB[r] = fmaf(dz, d3, sP[r]);
        __syncthreads();

        float d4 = deriv(sB);
        if (lane == 0) {
            float ksum = d1 + 2.f * d2 + 2.f * d3 + d4;
            float Pn   = fmaf(sixth_dz, ksum, sP[r]);
            sP[r] = Pn;
            sA[r] = Pn;
        }
        __syncthreads();
    }

    // ---- write signal channels ----
    if (tid < NC) out[b * NC + tid] = sP[NP + tid];
}

extern "C" void kernel_launch(void* const* d_in, const int* in_sizes, int n_in,
                              void* d_out, int out_size)
{
    const float* x   = (const float*)d_in[0];   // (4096, 8)
    const float* rr  = (const float*)d_in[1];   // (801,)
    const float* swl = (const float*)d_in[2];   // (100,)
    float* out = (float*)d_out;                 // (4096, 100)

    int batch = in_sizes[0] / (2 * NP);
    raman_kernel<<<batch, THREADS>>>(x, rr, swl, out);
}

// round 2
// speedup vs baseline: 2.0856x; 2.0856x over previous
#include <cuda_runtime.h>

// RamanAmplifier on GB300: 4096 independent RK4 integrations of
// dP/dz = (G P - loss) .* P, G = 104x104 per batch element.
// R2 design: 4 batch elems/CTA, 416 threads = 13 full warps.
// Thread = (elem e, row-group g, lane l): owns rows g*4..g*4+3 restricted to
// cols l*28..l*28+27. G slice (112 floats) lives in registers packed as f32x2;
// stage argument vector lives in shared (double buffered); own-row P and
// stage-arg live in registers. Matvec uses packed fma.rn.f32x2 (FFMA2).

#define NP 4
#define NC 100
#define NT 104
#define NPAD 112
#define ELEMS 4
#define TPE 104
#define THREADS 416
#define NSTEPS 499
#define RESP_LEN 801

typedef unsigned long long u64;

__device__ __forceinline__ u64 pk2(float lo, float hi) {
    u64 r; asm("mov.b64 %0,{%1,%2};" : "=l"(r) : "f"(lo), "f"(hi)); return r;
}
__device__ __forceinline__ void upk2(float& lo, float& hi, u64 v) {
    asm("mov.b64 {%0,%1},%2;" : "=f"(lo), "=f"(hi) : "l"(v));
}
__device__ __forceinline__ void ffma2(u64& d, u64 a, u64 b) {
    asm("fma.rn.f32x2 %0,%1,%2,%3;" : "=l"(d) : "l"(a), "l"(b), "l"(d));
}

__global__ __launch_bounds__(THREADS, 1)
void raman_kernel(const float* __restrict__ x,
                  const float* __restrict__ rr,
                  const float* __restrict__ swl,
                  float* __restrict__ out)
{
    __shared__ float sF[ELEMS * NPAD];
    __shared__ float sA[ELEMS * NPAD];
    __shared__ float sB[ELEMS * NPAD];
    __shared__ float sRR[RESP_LEN];

    const int tid  = threadIdx.x;
    const int e    = tid / TPE;          // batch element within CTA (0..3)
    const int t    = tid % TPE;
    const int g    = t >> 2;             // row group (0..25)
    const int lane = t & 3;              // column lane (0..3)
    const int rown = g * 4 + lane;       // row this thread finally owns
    const int j0   = lane * 28;          // column slice start

    // ---- raman response to shared ----
    for (int i = tid; i < RESP_LEN; i += THREADS) sRR[i] = rr[i];

    // ---- frequencies + initial power (all elems), pads zeroed ----
    for (int i = tid; i < ELEMS * NPAD; i += THREADS) {
        int ee = i / NPAD, ii = i % NPAD;
        const float* xb = x + (blockIdx.x * ELEMS + ee) * (2 * NP);
        float f = 0.f, p0 = 0.f;
        if (ii < NT) {
            float lam = (ii < NP) ? xb[ii] : swl[ii - NP];
            f  = __fdiv_rn(299792458.0f, lam);
            p0 = (ii < NP) ? fabsf(xb[NP + ii]) : 0.001f;
        }
        sF[i] = f; sA[i] = p0; sB[i] = 0.f;
    }
    __syncthreads();

    const float loss = 0.0002f * 0.23025851f;   // only c2 term nonzero

    // ---- G slice: rows g*4+k (k=0..3), cols j0..j0+27, packed f32x2 ----
    u64 Gp[56];
    #pragma unroll
    for (int k = 0; k < 4; k++) {
        float fr = sF[e * NPAD + g * 4 + k];
        #pragma unroll
        for (int c = 0; c < 14; c++) {
            float gv[2];
            #pragma unroll
            for (int h = 0; h < 2; h++) {
                int j = j0 + 2 * c + h;
                float v = 0.f;
                if (j < NT) {
                    float fj   = sF[e * NPAD + j];
                    float D    = fj - fr;
                    float fidx = __fdiv_rn(fabsf(D), 50000000000.0f);
                    float fi0  = floorf(fidx);
                    if (fi0 > 799.f) fi0 = 799.f;
                    int   i0   = (int)fi0;
                    float w    = fidx - fi0;
                    float gg   = sRR[i0] * (1.f - w) + sRR[i0 + 1] * w;
                    if (D < 0.f) gg = -gg;
                    float ratio = __fdiv_rn(fr, fj);
                    v = __fdiv_rn(gg * fmaxf(1.f, ratio), 8e-11f);
                }
                gv[h] = v;
            }
            Gp[k * 14 + c] = pk2(gv[0], gv[1]);
        }
    }

    float Pown = sA[e * NPAD + rown];    // own-row power, kept in register

    const double dzd = 50000.0 / 499.0;
    const float  dz       = (float)dzd;
    const float  half_dz  = (float)(0.5 * dzd);
    const float  sixth_dz = (float)(dzd / 6.0);

    const float* pA = sA + e * NPAD + j0;
    const float* pB = sB + e * NPAD + j0;
    float* wA = sA + e * NPAD + rown;
    float* wB = sB + e * NPAD + rown;

    // deriv for own row given stage-arg buffer slice and own-row arg value
    auto stagederiv = [&](const float* buf, float argown) -> float {
        u64 a0 = 0, a1 = 0, a2 = 0, a3 = 0;
        const ulonglong2* v = reinterpret_cast<const ulonglong2*>(buf);
        #pragma unroll
        for (int u = 0; u < 7; u++) {
            ulonglong2 p = v[u];
            ffma2(a0, Gp[     2*u], p.x); ffma2(a0, Gp[     2*u + 1], p.y);
            ffma2(a1, Gp[14 + 2*u], p.x); ffma2(a1, Gp[14 + 2*u + 1], p.y);
            ffma2(a2, Gp[28 + 2*u], p.x); ffma2(a2, Gp[28 + 2*u + 1], p.y);
            ffma2(a3, Gp[42 + 2*u], p.x); ffma2(a3, Gp[42 + 2*u + 1], p.y);
        }
        float l0,h0,l1,h1,l2,h2,l3,h3;
        upk2(l0,h0,a0); upk2(l1,h1,a1); upk2(l2,h2,a2); upk2(l3,h3,a3);
        float s0 = l0 + h0, s1 = l1 + h1, s2 = l2 + h2, s3 = l3 + h3;
        // reduce-scatter over the 4 lanes of this group (3 shuffles)
        bool hi2 = lane & 2;
        float recvA = __shfl_xor_sync(0xffffffffu, hi2 ? s0 : s2, 2);
        float recvB = __shfl_xor_sync(0xffffffffu, hi2 ? s1 : s3, 2);
        float t0 = (hi2 ? s2 : s0) + recvA;     // rows {0,1} or {2,3} half-sums
        float t1 = (hi2 ? s3 : s1) + recvB;
        bool hi1 = lane & 1;
        float recvC = __shfl_xor_sync(0xffffffffu, hi1 ? t0 : t1, 1);
        float dot = (hi1 ? t1 : t0) + recvC;    // full dot for row g*4+lane
        return (dot - loss) * argown;
    };

    for (int step = 0; step < NSTEPS; step++) {
        // stage 1: arg = P (held in sA; own value = Pown)
        float d1 = stagederiv(pA, Pown);
        float a2v = fmaf(half_dz, d1, Pown);
        *wB = a2v;
        __syncthreads();

        // stage 2
        float d2 = stagederiv(pB, a2v);
        float a3v = fmaf(half_dz, d2, Pown);
        *wA = a3v;
        __syncthreads();

        // stage 3
        float d3 = stagederiv(pA, a3v);
        float a4v = fmaf(dz, d3, Pown);
        *wB = a4v;
        __syncthreads();

        // stage 4 + combine
        float d4 = stagederiv(pB, a4v);
        Pown = fmaf(sixth_dz, d1 + 2.f * d2 + 2.f * d3 + d4, Pown);
        *wA = Pown;
        __syncthreads();
    }

    if (rown >= NP)
        out[(blockIdx.x * ELEMS + e) * NC + (rown - NP)] = Pown;
}

extern "C" void kernel_launch(void* const* d_in, const int* in_sizes, int n_in,
                              void* d_out, int out_size)
{
    const float* x   = (const float*)d_in[0];   // (4096, 8)
    const float* rr  = (const float*)d_in[1];   // (801,)
    const float* swl = (const float*)d_in[2];   // (100,)
    float* out = (float*)d_out;                 // (4096, 100)

    int batch = in_sizes[0] / (2 * NP);
    raman_kernel<<<batch / ELEMS, THREADS>>>(x, rr, swl, out);
}